// round 14
// baseline (speedup 1.0000x reference)
#include <cuda_runtime.h>
#include <cuda_bf16.h>

// ---------------------------------------------------------------------------
// HierarchicalRefinementQuantizer: B=4096, H=3, K=32768, D=128
//   per head: c = argmax_k -(||r||^2 + ||W_k||^2 - 2 r.W_k);  r -= W_c;  q += W_c
// bf16 mma.sync GEMM (legacy tensor path is the sm_103 ceiling here; tcgen05
// is unavailable: harness PTX target is compute_103 without the 'a' suffix).
// PERSISTENT grid (296 CTAs = 2/SM) sweeps contiguous (chunk, mtile) tiles to
// remove wave quantization; B tile reloaded only at chunk boundaries.
// Produces per-32-code group maxima. Rescore: smem-staged thread-per-code
// fp32 compensated dot (TwoProdFMA + TwoSum, 4 accumulators) emulating the
// reference's fp32 rounding: s = -( fl(fl(A)+fl(Bk)) - fl(2*dot) ).
// ---------------------------------------------------------------------------

#define B_N 4096
#define D_N 128
#define H_N 3
#define K_N 32768
#define MT  128                  // M tile
#define NT  128                  // N tile (chunk width)
#define NCHUNKS (K_N / NT)       // 256
#define NGROUPS (K_N / 32)       // 1024
#define NTILES  (NCHUNKS * (B_N / MT))   // 8192 (chunk-major: t = chunk*32 + mtile)
#define NCTA    296              // 2 per SM, one wave
#define SROW 72                  // padded smem row stride (bf16) = 144B
#define GEMM_SMEM ((2 * NT * SROW + 4 * MT * SROW) * 2)   // 110592 bytes
#define RESC_SMEM (128 * 129 * 4)                          // 66048 bytes

// ------------------------- device scratch (no allocs) ----------------------
__device__ __align__(128) __nv_bfloat16 g_Bbig[H_N][K_N][128];  // 25.2 MB
__device__ __align__(128) __nv_bfloat16 g_Abig[B_N][128];       // 1.0 MB
__device__ float g_wnorm [H_N][K_N];   // 0.5*||W||^2 (fp32, GEMM bias)
__device__ float g_wnormf[H_N][K_N];   // fl(||W||^2) (fp32, rescore)
__device__ float g_resid[B_N][D_N];
__device__ float g_quant[B_N][D_N];
__device__ __align__(16) float g_pval[B_N][NGROUPS];            // 16 MB

// ------------------------- helpers -----------------------------------------
__device__ __forceinline__ void cp16(void* smem_dst, const void* gsrc) {
    unsigned s = (unsigned)__cvta_generic_to_shared(smem_dst);
    asm volatile("cp.async.cg.shared.global [%0], [%1], 16;\n" :: "r"(s), "l"(gsrc));
}

__device__ __forceinline__ void mma16816(float* d, const unsigned* a, const unsigned* b) {
    asm volatile(
        "mma.sync.aligned.m16n8k16.row.col.f32.bf16.bf16.f32 "
        "{%0,%1,%2,%3}, {%4,%5,%6,%7}, {%8,%9}, {%0,%1,%2,%3};\n"
        : "+f"(d[0]), "+f"(d[1]), "+f"(d[2]), "+f"(d[3])
        : "r"(a[0]), "r"(a[1]), "r"(a[2]), "r"(a[3]), "r"(b[0]), "r"(b[1]));
}

// compensated accumulate: (s,c) += a*b  (TwoProdFMA + TwoSum)
__device__ __forceinline__ void dot2_acc(float a, float b, float& s, float& c) {
    float p = a * b;
    float ep = __fmaf_rn(a, b, -p);
    float t = s + p;
    float z = t - s;
    float es = (s - (t - z)) + (p - z);
    s = t;
    c += ep + es;
}

// ------------------------- prep: bf16 emb + norms ---------------------------
__global__ void hrq_prep_b(const float* __restrict__ emb) {
    int wg = (blockIdx.x * blockDim.x + threadIdx.x) >> 5;
    int lane = threadIdx.x & 31;
    if (wg >= H_N * K_N) return;
    int h = wg / K_N;
    int k = wg % K_N;
    const float* w = emb + ((size_t)h * K_N + k) * D_N;
    double ssum = 0.0;
#pragma unroll
    for (int j = 0; j < 4; j++) {
        int d = lane + 32 * j;
        float x = w[d];
        g_Bbig[h][k][d] = __float2bfloat16_rn(x);
        ssum += (double)x * (double)x;
    }
#pragma unroll
    for (int off = 16; off; off >>= 1)
        ssum += __shfl_xor_sync(0xffffffffu, ssum, off);
    if (lane == 0) {
        g_wnorm [h][k] = 0.5f * (float)ssum;
        g_wnormf[h][k] = (float)ssum;
    }
}

// ------------------------- init: residual + A + loss ------------------------
__global__ void hrq_init(const float* __restrict__ inputs, float* __restrict__ out,
                         long long off_loss) {
    int idx = blockIdx.x * blockDim.x + threadIdx.x;
    if (idx >= B_N * D_N) return;
    int row = idx / D_N, d = idx % D_N;
    float x = inputs[idx];
    g_resid[row][d] = x;
    g_quant[row][d] = 0.f;
    g_Abig[row][d]  = __float2bfloat16_rn(x);
    if (off_loss >= 0 && d == 0) out[off_loss + row] = 0.f;
}

// ---------- GEMM: persistent CTAs over contiguous (chunk, mtile) tiles ------
extern __shared__ char hrq_smem[];

__global__ __launch_bounds__(256, 2) void hrq_gemm_argmax(int h) {
    const int wcta = blockIdx.x;                         // 0..NCTA-1
    const int t0 = (int)(((long long)NTILES * wcta) / NCTA);
    const int t1 = (int)(((long long)NTILES * (wcta + 1)) / NCTA);

    __nv_bfloat16* Bs = (__nv_bfloat16*)hrq_smem;        // [2 kc][128][SROW]
    __nv_bfloat16* As = Bs + 2 * NT * SROW;              // [2 st][2 kc][128][SROW]
    __shared__ float sval[MT * 4];

    const int tid  = threadIdx.x;
    const int lrow = tid >> 1;
    const int lseg = (tid & 1) * 32;

    auto issueB = [&](int chunk) {
#pragma unroll
        for (int kc = 0; kc < 2; kc++) {
            const __nv_bfloat16* gb = &g_Bbig[h][chunk * NT + lrow][kc * 64 + lseg];
            __nv_bfloat16* sb = Bs + kc * NT * SROW + lrow * SROW + lseg;
#pragma unroll
            for (int j = 0; j < 4; j++) cp16(sb + j * 8, gb + j * 8);
        }
        asm volatile("cp.async.commit_group;\n");
    };
    auto issueA = [&](int t, int st) {
        const int mbase = (t & 31) * MT;
#pragma unroll
        for (int kc = 0; kc < 2; kc++) {
            const __nv_bfloat16* ga = &g_Abig[mbase + lrow][kc * 64 + lseg];
            __nv_bfloat16* sa = As + (st * 2 + kc) * MT * SROW + lrow * SROW + lseg;
#pragma unroll
            for (int j = 0; j < 4; j++) cp16(sa + j * 8, ga + j * 8);
        }
        asm volatile("cp.async.commit_group;\n");
    };

    const int w  = tid >> 5, lane = tid & 31;
    const int wm = w & 3,  wn = w >> 2;       // 4x2 warp grid, warp tile 32x64
    const int g  = lane >> 2, l = lane & 3;

    // prologue: B(chunk of t0), A(t0), A(t0+1)   (t1-t0 >= 27 always)
    issueB(t0 >> 5);
    issueA(t0, 0);
    issueA(t0 + 1, 1);
    asm volatile("cp.async.wait_group 1;\n");   // B + A(t0) complete
    __syncthreads();

    float bias[8][2];
    int biaschunk = -1;

    for (int m = t0; m < t1; m++) {
        const int st    = (m - t0) & 1;
        const int chunk = m >> 5;
        if (chunk != biaschunk) {
            biaschunk = chunk;
            const int n0 = chunk * NT;
#pragma unroll
            for (int nb = 0; nb < 8; nb++)
#pragma unroll
                for (int j = 0; j < 2; j++)
                    bias[nb][j] = g_wnorm[h][n0 + wn * 64 + nb * 8 + 2 * l + j];
        }

        float acc[2][8][4];
#pragma unroll
        for (int a = 0; a < 2; a++)
#pragma unroll
            for (int b = 0; b < 8; b++)
#pragma unroll
                for (int c = 0; c < 4; c++) acc[a][b][c] = 0.f;

#pragma unroll
        for (int kc = 0; kc < 2; kc++) {
            const __nv_bfloat16* Ab = As + (st * 2 + kc) * MT * SROW;
            const __nv_bfloat16* Bb = Bs + kc * NT * SROW;
#pragma unroll
            for (int ks = 0; ks < 64; ks += 16) {
                unsigned afr[2][4];
#pragma unroll
                for (int mb = 0; mb < 2; mb++) {
                    const int R = wm * 32 + mb * 16;
                    afr[mb][0] = *(const unsigned*)(Ab + (R + g) * SROW + ks + 2 * l);
                    afr[mb][1] = *(const unsigned*)(Ab + (R + g + 8) * SROW + ks + 2 * l);
                    afr[mb][2] = *(const unsigned*)(Ab + (R + g) * SROW + ks + 2 * l + 8);
                    afr[mb][3] = *(const unsigned*)(Ab + (R + g + 8) * SROW + ks + 2 * l + 8);
                }
#pragma unroll
                for (int nb = 0; nb < 8; nb++) {
                    unsigned bfr[2];
                    const int C = wn * 64 + nb * 8 + g;
                    bfr[0] = *(const unsigned*)(Bb + C * SROW + ks + 2 * l);
                    bfr[1] = *(const unsigned*)(Bb + C * SROW + ks + 2 * l + 8);
                    mma16816(acc[0][nb], afr[0], bfr);
                    mma16816(acc[1][nb], afr[1], bfr);
                }
            }
        }
        __syncthreads();                       // stage st + B reads complete

        // tail issues: B first (so wait_group 1 forces it), then A prefetch
        const bool bsw = (m + 1 < t1) && (((m + 1) >> 5) != chunk);
        if (bsw) issueB((m + 1) >> 5);
        const bool pre = (m + 2 < t1);
        if (pre) issueA(m + 2, st);

        // ---- epilogue: per-32-code group maxima (bias applied per code) ----
#pragma unroll
        for (int mb = 0; mb < 2; mb++) {
#pragma unroll
            for (int half = 0; half < 2; half++) {
                float gm[2] = {-3.4e38f, -3.4e38f};
#pragma unroll
                for (int nb = 0; nb < 8; nb++) {
#pragma unroll
                    for (int j = 0; j < 2; j++) {
                        float v = acc[mb][nb][half * 2 + j] - bias[nb][j];
                        gm[nb >> 2] = fmaxf(gm[nb >> 2], v);
                    }
                }
#pragma unroll
                for (int off = 1; off <= 2; off <<= 1) {
                    gm[0] = fmaxf(gm[0], __shfl_xor_sync(0xffffffffu, gm[0], off));
                    gm[1] = fmaxf(gm[1], __shfl_xor_sync(0xffffffffu, gm[1], off));
                }
                if (l == 0) {
                    int rloc = wm * 32 + mb * 16 + half * 8 + g;
                    sval[rloc * 4 + wn * 2 + 0] = gm[0];
                    sval[rloc * 4 + wn * 2 + 1] = gm[1];
                }
            }
        }
        if (pre) { asm volatile("cp.async.wait_group 1;\n"); }  // A(m+1)+B done
        else     { asm volatile("cp.async.wait_group 0;\n"); }
        __syncthreads();                       // sval ready + next tiles visible
        if (tid < MT) {
            float4 v4 = *(float4*)&sval[tid * 4];
            *(float4*)&g_pval[(m & 31) * MT + tid][chunk * 4] = v4;
        }
    }
}

// ---- rescore: smem-staged thread-per-code, fp32 compensated dot ------------
__global__ __launch_bounds__(128) void hrq_reduce_update(
        const float* __restrict__ emb, float* __restrict__ out,
        int h, long long off_q, long long off_c, float delta) {
    const int row = blockIdx.x;
    const int tid = threadIdx.x;
    const int wid = tid >> 5, lane = tid & 31;
    float* sw = (float*)hrq_smem;              // [128 codes][129] staged W

    __shared__ float sres[D_N];
    __shared__ float swred[4];
    __shared__ double sdred[4];
    __shared__ float ssc[4];
    __shared__ int   sci[4];
    __shared__ float s_bcast;
    __shared__ int   s_code;
    __shared__ int   s_cand[NGROUPS];
    __shared__ int   s_ncand;

    if (tid == 0) s_ncand = 0;
    float rv = g_resid[row][tid];
    sres[tid] = rv;

    float4 pa = __ldg((const float4*)&g_pval[row][tid * 8]);
    float4 pb = __ldg((const float4*)&g_pval[row][tid * 8 + 4]);
    float pv[8] = {pa.x, pa.y, pa.z, pa.w, pb.x, pb.y, pb.z, pb.w};

    // fl(A) = fp64 ||r||^2 (1 DFMA/thread) + group-partial max
    double rr = (double)rv * (double)rv;
    float  mv = pv[0];
#pragma unroll
    for (int j = 1; j < 8; j++) mv = fmaxf(mv, pv[j]);
#pragma unroll
    for (int off = 16; off; off >>= 1) {
        rr += __shfl_xor_sync(0xffffffffu, rr, off);
        mv  = fmaxf(mv, __shfl_xor_sync(0xffffffffu, mv, off));
    }
    if (lane == 0) { sdred[wid] = rr; swred[wid] = mv; }
    __syncthreads();
    if (tid == 0) {
        double rrt = (sdred[0] + sdred[1]) + (sdred[2] + sdred[3]);
        float  mvt = fmaxf(fmaxf(swred[0], swred[1]), fmaxf(swred[2], swred[3]));
        s_bcast = mvt;
        swred[0] = (float)rrt;      // fl(A)
    }
    __syncthreads();
    const float rr_f   = swred[0];
    const float thresh = s_bcast - delta;

    // gather candidate groups (order-independent: selection is (sc, min-idx))
#pragma unroll
    for (int j = 0; j < 8; j++)
        if (pv[j] >= thresh) s_cand[atomicAdd(&s_ncand, 1)] = tid * 8 + j;
    __syncthreads();
    const int ncand = s_ncand;
    const float* embh = emb + (size_t)h * K_N * D_N;

    float bestsc = -3.4e38f;
    int   besti  = 0x7fffffff;
    for (int ci = 0; ci < ncand; ci += 4) {
        const int nthis  = min(4, ncand - ci);
        const int ncodes = nthis * 32;
        // stage W rows for up to 128 candidate codes (coalesced; stride 129)
        for (int i = tid; i < ncodes * D_N; i += 128) {
            int rrow = i >> 7;                 // all threads share rrow per iter
            int gidx = s_cand[ci + (rrow >> 5)];
            int code = gidx * 32 + (rrow & 31);
            sw[rrow * 129 + tid] = __ldg(embh + (size_t)code * D_N + tid);
        }
        __syncthreads();
        if (tid < ncodes) {
            int gidx = s_cand[ci + (tid >> 5)];
            int code = gidx * 32 + (tid & 31);
            const float* wr = &sw[tid * 129];
            float s0 = 0.f, c0 = 0.f, s1 = 0.f, c1 = 0.f;
            float s2 = 0.f, c2 = 0.f, s3 = 0.f, c3 = 0.f;
#pragma unroll
            for (int d = 0; d < D_N; d += 4) {
                dot2_acc(sres[d + 0], wr[d + 0], s0, c0);
                dot2_acc(sres[d + 1], wr[d + 1], s1, c1);
                dot2_acc(sres[d + 2], wr[d + 2], s2, c2);
                dot2_acc(sres[d + 3], wr[d + 3], s3, c3);
            }
            // compensated pairwise merge of the 4 (s,c) pairs (R11-proven)
            float t, z, e, sm01, cm01, sm23, cm23, sm, cm;
            t = s0 + s1; z = t - s0; e = (s0 - (t - z)) + (s1 - z);
            sm01 = t; cm01 = c0 + c1 + e;
            t = s2 + s3; z = t - s2; e = (s2 - (t - z)) + (s3 - z);
            sm23 = t; cm23 = c2 + c3 + e;
            t = sm01 + sm23; z = t - sm01; e = (sm01 - (t - z)) + (sm23 - z);
            sm = t; cm = cm01 + cm23 + e;
            float dot = sm + cm;               // fl(dot), twice-precision
            // Reference fp32 emulation: s = -( fl(fl(A)+fl(Bk)) - fl(2*dot) )
            float X  = rr_f + __ldg(&g_wnormf[h][code]);
            float sc = -(X - 2.0f * dot);
            if (sc > bestsc || (sc == bestsc && code < besti)) { bestsc = sc; besti = code; }
        }
        __syncthreads();
    }
    // block argmax (tie -> lowest index)
#pragma unroll
    for (int off = 16; off; off >>= 1) {
        float ov = __shfl_xor_sync(0xffffffffu, bestsc, off);
        int   oi = __shfl_xor_sync(0xffffffffu, besti, off);
        if (ov > bestsc || (ov == bestsc && oi < besti)) { bestsc = ov; besti = oi; }
    }
    if (lane == 0) { ssc[wid] = bestsc; sci[wid] = besti; }
    __syncthreads();
    if (tid == 0) {
        float bs = ssc[0]; int bi = sci[0];
#pragma unroll
        for (int j = 1; j < 4; j++) {
            if (ssc[j] > bs || (ssc[j] == bs && sci[j] < bi)) { bs = ssc[j]; bi = sci[j]; }
        }
        s_code = bi;
    }
    __syncthreads();
    const int c = s_code;

    // residual / quantized update with exact fp32 rows (reference order)
    {
        float wv = embh[(size_t)c * D_N + tid];
        float r  = g_resid[row][tid] - wv;
        float q  = g_quant[row][tid] + wv;
        g_resid[row][tid] = r;
        g_quant[row][tid] = q;
        if (h < H_N - 1) {
            g_Abig[row][tid] = __float2bfloat16_rn(r);
        } else {
            out[off_q + (long long)row * D_N + tid] = q;
        }
    }
    if (off_c >= 0 && tid == 0)
        out[off_c + (long long)row * H_N + h] = (float)c;
}

// ------------------------- launch ------------------------------------------
extern "C" void kernel_launch(void* const* d_in, const int* in_sizes, int n_in,
                              void* d_out, int out_size) {
    const float* inputs = (const float*)d_in[0];
    const float* emb    = (const float*)d_in[1];
    if (n_in >= 2 && in_sizes[0] > in_sizes[1]) {
        inputs = (const float*)d_in[1];
        emb    = (const float*)d_in[0];
    }
    float* out = (float*)d_out;

    long long off_l = -1, off_q = 0, off_c = -1;
    if (out_size == B_N + B_N * D_N + B_N * H_N) {
        off_l = 0; off_q = B_N; off_c = (long long)B_N + (long long)B_N * D_N;
    } else if (out_size == B_N * D_N + B_N * H_N) {
        off_q = 0; off_c = (long long)B_N * D_N;
    }

    cudaFuncSetAttribute(hrq_gemm_argmax,
                         cudaFuncAttributeMaxDynamicSharedMemorySize, GEMM_SMEM);
    cudaFuncSetAttribute(hrq_reduce_update,
                         cudaFuncAttributeMaxDynamicSharedMemorySize, RESC_SMEM);

    // rescan window on the v = dot - 0.5||W||^2 scale: >25 sigma of bf16 noise
    const float deltas[H_N] = {0.03f, 0.015f, 0.0075f};

    hrq_prep_b<<<(H_N * K_N) / 8, 256>>>(emb);
    hrq_init<<<(B_N * D_N + 255) / 256, 256>>>(inputs, out, off_l);
    for (int h = 0; h < H_N; h++) {
        hrq_gemm_argmax<<<NCTA, 256, GEMM_SMEM>>>(h);
        hrq_reduce_update<<<B_N, 128, RESC_SMEM>>>(emb, out, h, off_q, off_c, deltas[h]);
    }
}